// round 17
// baseline (speedup 1.0000x reference)
#include <cuda_runtime.h>
#include <cuda_fp16.h>
#include <cstdint>

#define D 128
#define MAXN 50176        // padded node capacity (actual N = 50000)
#define MAXE 600000
#define SCAN_BLK 512
#define NSCAN (MAXN / SCAN_BLK)   // 98

// ---------------- scratch (no allocs allowed) ----------------
__device__ int   g_cnt[MAXN];          // zeroed in scan1 (self-restoring)
__device__ int   g_fill[MAXN];         // set by scan3 to row start each call
__device__ int   g_row[MAXN + 1];
__device__ int   g_bsum[NSCAN];
__device__ int   g_csrc[MAXE];
__device__ float g_inv[MAXN];
__device__ float g_hop1[MAXN * D];
__device__ float g_hop2[MAXN * D];

// ---------------- in-degree histogram (4 edges/thread) ----------------
__global__ void degree_kernel(const int* __restrict__ ei, int E) {
    int i = blockIdx.x * blockDim.x + threadIdx.x;
    if (i < E / 4) {
        int4 d4 = ((const int4*)(ei + E))[i];
        atomicAdd(&g_cnt[d4.x], 1);
        atomicAdd(&g_cnt[d4.y], 1);
        atomicAdd(&g_cnt[d4.z], 1);
        atomicAdd(&g_cnt[d4.w], 1);
    }
}

// ---------------- scan1: per-block exclusive prefix, block sum, inv-degree ----------------
__global__ void scan1_kernel() {
    __shared__ int sh[SCAN_BLK];
    int t = threadIdx.x;
    int i = blockIdx.x * SCAN_BLK + t;
    int v = g_cnt[i];
    g_cnt[i] = 0;                              // self-restore for next replay
    sh[t] = v;
    __syncthreads();
#pragma unroll
    for (int off = 1; off < SCAN_BLK; off <<= 1) {
        int u = (t >= off) ? sh[t - off] : 0;
        __syncthreads();
        sh[t] += u;
        __syncthreads();
    }
    g_row[i] = sh[t] - v;                      // exclusive within block
    g_inv[i] = 1.0f / fmaxf((float)v, 1.0f);
    if (t == SCAN_BLK - 1) g_bsum[blockIdx.x] = sh[t];
}

// ---------------- scan3: add block offsets (redundant per-block scan of bsum) ----------------
__global__ void scan3_kernel() {
    __shared__ int sh[128];
    int t = threadIdx.x;
    if (t < 128) sh[t] = (t < NSCAN) ? g_bsum[t] : 0;
    __syncthreads();
#pragma unroll
    for (int off = 1; off < 128; off <<= 1) {
        int u = (t < 128 && t >= off) ? sh[t - off] : 0;
        __syncthreads();
        if (t < 128) sh[t] += u;
        __syncthreads();
    }
    int offset = (blockIdx.x == 0) ? 0 : sh[blockIdx.x - 1];
    int i = blockIdx.x * SCAN_BLK + t;
    int r = g_row[i] + offset;
    g_row[i] = r;
    g_fill[i] = r;
}

// ---------------- CSR fill (4 edges/thread) ----------------
__global__ void fill_kernel(const int* __restrict__ ei, int E) {
    int i = blockIdx.x * blockDim.x + threadIdx.x;
    if (i < E / 4) {
        int4 s4 = ((const int4*)ei)[i];
        int4 d4 = ((const int4*)(ei + E))[i];
        int p0 = atomicAdd(&g_fill[d4.x], 1);
        int p1 = atomicAdd(&g_fill[d4.y], 1);
        int p2 = atomicAdd(&g_fill[d4.z], 1);
        int p3 = atomicAdd(&g_fill[d4.w], 1);
        g_csrc[p0] = s4.x;
        g_csrc[p1] = s4.y;
        g_csrc[p2] = s4.z;
        g_csrc[p3] = s4.w;
    }
}

// ---------------- mean aggregation (pull): one warp per dst node, MLP=8 ----------------
__global__ void hop_kernel(const float* __restrict__ x, int pass, int n) {
    int w = (blockIdx.x * blockDim.x + threadIdx.x) >> 5;
    if (w >= n) return;
    int lane = threadIdx.x & 31;

    const float4* in = (pass == 0) ? (const float4*)x : (const float4*)g_hop1;
    float*        op = (pass == 0) ? g_hop1 : g_hop2;

    int beg = g_row[w];
    int end = g_row[w + 1];

    float ax = 0.f, ay = 0.f, az = 0.f, aw = 0.f;
    int j = beg;
    // 8-wide batches: 8 independent index loads, then 8 independent gathers
    for (; j + 8 <= end; j += 8) {
        int s0 = __ldg(&g_csrc[j + 0]);
        int s1 = __ldg(&g_csrc[j + 1]);
        int s2 = __ldg(&g_csrc[j + 2]);
        int s3 = __ldg(&g_csrc[j + 3]);
        int s4 = __ldg(&g_csrc[j + 4]);
        int s5 = __ldg(&g_csrc[j + 5]);
        int s6 = __ldg(&g_csrc[j + 6]);
        int s7 = __ldg(&g_csrc[j + 7]);
        float4 v0 = __ldg(in + (size_t)s0 * 32 + lane);
        float4 v1 = __ldg(in + (size_t)s1 * 32 + lane);
        float4 v2 = __ldg(in + (size_t)s2 * 32 + lane);
        float4 v3 = __ldg(in + (size_t)s3 * 32 + lane);
        float4 v4 = __ldg(in + (size_t)s4 * 32 + lane);
        float4 v5 = __ldg(in + (size_t)s5 * 32 + lane);
        float4 v6 = __ldg(in + (size_t)s6 * 32 + lane);
        float4 v7 = __ldg(in + (size_t)s7 * 32 + lane);
        ax += v0.x; ay += v0.y; az += v0.z; aw += v0.w;
        ax += v1.x; ay += v1.y; az += v1.z; aw += v1.w;
        ax += v2.x; ay += v2.y; az += v2.z; aw += v2.w;
        ax += v3.x; ay += v3.y; az += v3.z; aw += v3.w;
        ax += v4.x; ay += v4.y; az += v4.z; aw += v4.w;
        ax += v5.x; ay += v5.y; az += v5.z; aw += v5.w;
        ax += v6.x; ay += v6.y; az += v6.z; aw += v6.w;
        ax += v7.x; ay += v7.y; az += v7.z; aw += v7.w;
    }
    // 4-wide tail batch
    if (j + 4 <= end) {
        int s0 = __ldg(&g_csrc[j + 0]);
        int s1 = __ldg(&g_csrc[j + 1]);
        int s2 = __ldg(&g_csrc[j + 2]);
        int s3 = __ldg(&g_csrc[j + 3]);
        float4 v0 = __ldg(in + (size_t)s0 * 32 + lane);
        float4 v1 = __ldg(in + (size_t)s1 * 32 + lane);
        float4 v2 = __ldg(in + (size_t)s2 * 32 + lane);
        float4 v3 = __ldg(in + (size_t)s3 * 32 + lane);
        ax += v0.x; ay += v0.y; az += v0.z; aw += v0.w;
        ax += v1.x; ay += v1.y; az += v1.z; aw += v1.w;
        ax += v2.x; ay += v2.y; az += v2.z; aw += v2.w;
        ax += v3.x; ay += v3.y; az += v3.z; aw += v3.w;
        j += 4;
    }
    for (; j < end; j++) {
        int s0 = __ldg(&g_csrc[j]);
        float4 v0 = __ldg(in + (size_t)s0 * 32 + lane);
        ax += v0.x; ay += v0.y; az += v0.z; aw += v0.w;
    }
    float inv = g_inv[w];
    float4 r = make_float4(ax * inv, ay * inv, az * inv, aw * inv);
    *((float4*)op + (size_t)w * 32 + lane) = r;
}

// ---------------- fp16 helpers ----------------
__device__ __forceinline__ uint32_t pack2h(float f0, float f1) {
    __half2 h = __floats2half2_rn(f0, f1);
    return *(uint32_t*)&h;
}

__device__ __forceinline__ void mma_f16(float* c, const uint32_t* a, const uint32_t* b) {
    asm volatile(
        "mma.sync.aligned.m16n8k16.row.col.f32.f16.f16.f32 "
        "{%0,%1,%2,%3}, {%4,%5,%6,%7}, {%8,%9}, {%0,%1,%2,%3};"
        : "+f"(c[0]), "+f"(c[1]), "+f"(c[2]), "+f"(c[3])
        : "r"(a[0]), "r"(a[1]), "r"(a[2]), "r"(a[3]), "r"(b[0]), "r"(b[1]));
}

// ---------------- HMMA fp16 fused concat-GEMM (single pass, proven R16) ----------------
#define SSTR 40   // padded fp16 row stride (conflict-free fragment LDS)
__global__ __launch_bounds__(256, 2)
void hmma_gemm_kernel(const float* __restrict__ x,
                      const float* __restrict__ W,     // [128, 384]
                      const float* __restrict__ bias,  // [128]
                      float* __restrict__ out, int n) {
    __shared__ __half Ah[128][SSTR];
    __shared__ __half Bh[128][SSTR];

    int tid = threadIdx.x;
    int wid = tid >> 5, lane = tid & 31;
    int wm = wid & 3;            // warp row:   m in [wm*32, +32)
    int wn = wid >> 2;           // warp col:   o in [wn*64, +64)
    int g = lane >> 2, tig = lane & 3;
    int m0 = blockIdx.x * 128;

    float acc[2][8][4];
#pragma unroll
    for (int mt = 0; mt < 2; mt++)
#pragma unroll
        for (int nt = 0; nt < 8; nt++)
#pragma unroll
            for (int q = 0; q < 4; q++) acc[mt][nt][q] = 0.f;

    int lrow = tid >> 1;                 // loader row 0..127
    int lh   = (tid & 1) * 16;           // k half within 32-chunk
    bool avalid = (m0 + lrow) < n;

#pragma unroll 1
    for (int kt = 0; kt < 12; kt++) {
        const float* A = (kt < 4) ? x : (kt < 8) ? g_hop1 : g_hop2;
        int ka = (kt & 3) * 32;

        float4 av[4], wv[4];
        const float4* ap = (const float4*)(A + (size_t)(m0 + lrow) * 128 + ka + lh);
        const float4* wp = (const float4*)(W + (size_t)lrow * 384 + kt * 32 + lh);
#pragma unroll
        for (int q = 0; q < 4; q++) {
            av[q] = avalid ? __ldg(ap + q) : make_float4(0.f, 0.f, 0.f, 0.f);
            wv[q] = __ldg(wp + q);
        }

        __syncthreads();   // previous tile fully consumed
#pragma unroll
        for (int q = 0; q < 4; q++) {
            int kc = lh + q * 4;
            *(uint32_t*)&Ah[lrow][kc]     = pack2h(av[q].x, av[q].y);
            *(uint32_t*)&Ah[lrow][kc + 2] = pack2h(av[q].z, av[q].w);
            *(uint32_t*)&Bh[lrow][kc]     = pack2h(wv[q].x, wv[q].y);
            *(uint32_t*)&Bh[lrow][kc + 2] = pack2h(wv[q].z, wv[q].w);
        }
        __syncthreads();

#pragma unroll
        for (int ks = 0; ks < 2; ks++) {
            int kb = ks * 16 + tig * 2;

            uint32_t bf[8][2];
#pragma unroll
            for (int nt = 0; nt < 8; nt++) {
                int nn = wn * 64 + nt * 8 + g;
                bf[nt][0] = *(const uint32_t*)&Bh[nn][kb];
                bf[nt][1] = *(const uint32_t*)&Bh[nn][kb + 8];
            }
#pragma unroll
            for (int mt = 0; mt < 2; mt++) {
                int am = wm * 32 + mt * 16 + g;
                uint32_t af[4];
                af[0] = *(const uint32_t*)&Ah[am][kb];
                af[1] = *(const uint32_t*)&Ah[am + 8][kb];
                af[2] = *(const uint32_t*)&Ah[am][kb + 8];
                af[3] = *(const uint32_t*)&Ah[am + 8][kb + 8];
#pragma unroll
                for (int nt = 0; nt < 8; nt++)
                    mma_f16(acc[mt][nt], af, bf[nt]);
            }
        }
    }

    // epilogue: acc -> out (+bias)
#pragma unroll
    for (int mt = 0; mt < 2; mt++) {
        int row = m0 + wm * 32 + mt * 16 + g;
#pragma unroll
        for (int nt = 0; nt < 8; nt++) {
            int col = wn * 64 + nt * 8 + tig * 2;
            float2 bb = *(const float2*)&bias[col];
            if (row < n) {
                float2 r0 = make_float2(acc[mt][nt][0] + bb.x, acc[mt][nt][1] + bb.y);
                *(float2*)&out[(size_t)row * 128 + col] = r0;
            }
            if (row + 8 < n) {
                float2 r1 = make_float2(acc[mt][nt][2] + bb.x, acc[mt][nt][3] + bb.y);
                *(float2*)&out[(size_t)(row + 8) * 128 + col] = r1;
            }
        }
    }
}

// ---------------- launch (single stream) ----------------
extern "C" void kernel_launch(void* const* d_in, const int* in_sizes, int n_in,
                              void* d_out, int out_size) {
    const float* x    = (const float*)d_in[0];
    const int*   ei   = (const int*)d_in[1];      // int32 (JAX x64 disabled)
    const float* W    = (const float*)d_in[2];
    const float* bias = (const float*)d_in[3];
    float*       out  = (float*)d_out;

    int n = in_sizes[0] / D;      // 50000
    int E = in_sizes[1] / 2;      // 600000

    // CSR build (by destination)
    degree_kernel<<<(E / 4 + 255) / 256, 256>>>(ei, E);
    scan1_kernel<<<NSCAN, SCAN_BLK>>>();
    scan3_kernel<<<NSCAN, SCAN_BLK>>>();
    fill_kernel<<<(E / 4 + 255) / 256, 256>>>(ei, E);

    // two mean-propagation hops (fp32, MLP=8)
    int hop_blocks = (n * 32 + 255) / 256;
    hop_kernel<<<hop_blocks, 256>>>(x, 0, n);
    hop_kernel<<<hop_blocks, 256>>>(x, 1, n);

    // fp16 HMMA GEMM, single accumulation pass
    hmma_gemm_kernel<<<(n + 127) / 128, 256>>>(x, W, bias, out, n);
}